// round 11
// baseline (speedup 1.0000x reference)
#include <cuda_runtime.h>
#include <cuda_bf16.h>
#include <stdint.h>

#define NSUP   1280
#define NQRY   65536
#define DIN    2048
#define DEMB   1024
#define NCLS   64
#define NSTEPS 5
#define QYB    (NQRY / 128)   // 512 query y-blocks

// ---------------- scratch (device globals; no allocation) ----------------
__device__ __align__(256) __nv_bfloat16 g_Wt[(size_t)DEMB * DIN];      // [DEMB][DIN]
__device__ __align__(256) __nv_bfloat16 g_qx[(size_t)NQRY * DIN];
__device__ __align__(256) __nv_bfloat16 g_sx[(size_t)NSUP * DIN];
__device__ __align__(256) __nv_bfloat16 g_qemb[(size_t)NQRY * DEMB];
__device__ __align__(256) __nv_bfloat16 g_semb[(size_t)NSUP * DEMB];
__device__ float g_qnorm[NQRY];
__device__ float g_ssum[NCLS * DEMB];
__device__ float g_scount[NCLS];
__device__ __align__(16) float g_qsum[NCLS * DEMB];
__device__ float g_qcount[NCLS];
__device__ __align__(256) __nv_bfloat16 g_pb[NCLS * DEMB];             // prototypes bf16
__device__ float g_pnorm[NCLS];

#define CP_ASYNC(dst, src) asm volatile("cp.async.cg.shared.global [%0], [%1], 16;\n" ::"r"(dst), "l"(src))
#define RED_V4(ptr, v) \
    asm volatile("red.global.add.v4.f32 [%0], {%1,%2,%3,%4};" \
                 ::"l"(ptr), "f"((v).x), "f"((v).y), "f"((v).z), "f"((v).w) : "memory")

// ---------------- small utility kernels ----------------
__global__ void k_convert(const float* __restrict__ x, __nv_bfloat16* __restrict__ y, int n4) {
    int i = blockIdx.x * blockDim.x + threadIdx.x;
    if (i < n4) {
        float4 v = ((const float4*)x)[i];
        ((__nv_bfloat162*)y)[2 * i + 0] = __floats2bfloat162_rn(v.x, v.y);
        ((__nv_bfloat162*)y)[2 * i + 1] = __floats2bfloat162_rn(v.z, v.w);
    }
}

// tiled transpose: W [DIN][DEMB] f32 -> Wt [DEMB][DIN] bf16.
// Side task: zeroes qnorm (65536), ssum (65536), scount (64).
__global__ void k_transpose_w(const float* __restrict__ W, __nv_bfloat16* __restrict__ Wt,
                              float* __restrict__ qnorm, float* __restrict__ ssum,
                              float* __restrict__ scount) {
    __shared__ float tile[32][33];
    int n0 = blockIdx.x * 32, k0 = blockIdx.y * 32;
#pragma unroll
    for (int i = 0; i < 4; i++) {
        int k = k0 + threadIdx.y + i * 8;
        tile[threadIdx.y + i * 8][threadIdx.x] = W[(size_t)k * DEMB + n0 + threadIdx.x];
    }
    {
        int bid = blockIdx.y * gridDim.x + blockIdx.x;  // 0..2047
        int t = threadIdx.y * 32 + threadIdx.x;         // 0..255
        if (t < 64) {
            int gi = bid * 64 + t;                      // 0..131071
            if (gi < NQRY) qnorm[gi] = 0.f;
            if (gi < NCLS * DEMB) ssum[gi] = 0.f;
            if (bid == 0 && t < NCLS) scount[t] = 0.f;
        }
    }
    __syncthreads();
#pragma unroll
    for (int i = 0; i < 4; i++) {
        int n = n0 + threadIdx.y + i * 8;
        Wt[(size_t)n * DIN + k0 + threadIdx.x] =
            __float2bfloat16(tile[threadIdx.x][threadIdx.y + i * 8]);
    }
}

__global__ void k_supp_stats(const __nv_bfloat16* __restrict__ semb, const int* __restrict__ lab,
                             float* __restrict__ ssum, float* __restrict__ scount) {
    int r = blockIdx.x;
    int L = lab[r];
    if (threadIdx.x == 0) atomicAdd(&scount[L], 1.0f);
    for (int c = threadIdx.x; c < DEMB; c += blockDim.x)
        atomicAdd(&ssum[L * DEMB + c], __bfloat162float(semb[(size_t)r * DEMB + c]));
}

// prototypes from (ssum [+ qsum]) / counts; ALSO zeroes qsum/qcount for the next pass.
__global__ void k_proto(const float* __restrict__ ssum, const float* __restrict__ scount,
                        float* __restrict__ qsum, float* __restrict__ qcount,
                        int useq, __nv_bfloat16* __restrict__ pb, float* __restrict__ pnorm) {
    int c = blockIdx.x;
    float cnt = scount[c] + (useq ? qcount[c] : 0.f);
    float inv = 1.f / fmaxf(cnt, 1.f);
    float s = 0.f;
    for (int j = threadIdx.x; j < DEMB; j += blockDim.x) {
        float p = (ssum[c * DEMB + j] + (useq ? qsum[c * DEMB + j] : 0.f)) * inv;
        qsum[c * DEMB + j] = 0.f;
        __nv_bfloat16 pv = __float2bfloat16(p);
        pb[c * DEMB + j] = pv;
        float pf = __bfloat162float(pv);
        s += pf * pf;
    }
    if (threadIdx.x == 0) qcount[c] = 0.f;
    __shared__ float red[8];
#pragma unroll
    for (int o2 = 16; o2; o2 >>= 1) s += __shfl_xor_sync(~0u, s, o2);
    if ((threadIdx.x & 31) == 0) red[threadIdx.x >> 5] = s;
    __syncthreads();
    if (threadIdx.x < 8) {
        s = red[threadIdx.x];
#pragma unroll
        for (int o2 = 4; o2; o2 >>= 1) s += __shfl_xor_sync(0xff, s, o2);
        if (threadIdx.x == 0) pnorm[c] = s;
    }
}

// ================= fused transductive step =================
// One CTA owns 512 query rows (grid 128 = single wave on 148 SMs).
// Phase A: HMMA GEMM q@p^T (K=1024), 3-stage, argmin margin -> labels in smem
// + qcount. Phase B: re-read own rows, accumulate per-class sums in 128KB
// float2 smem bins (4 row-groups of 128 rows), flush via red.global.add.v4.f32.
#define STP_BM    512
#define STP_STAGE ((STP_BM + 64) * 128)   // 73728 B per stage
#define STP_SMEM  (3 * STP_STAGE)         // 221184 B (>= bins 131072)

__global__ void __launch_bounds__(256, 1) k_step(
    const __nv_bfloat16* __restrict__ qemb, const __nv_bfloat16* __restrict__ pb,
    const float* __restrict__ pnorm, float* __restrict__ qsum, float* __restrict__ qcount) {
    extern __shared__ char smem_raw[];
    uint32_t sbase = (uint32_t)__cvta_generic_to_shared(smem_raw);
    __shared__ short labels_s[STP_BM];
    __shared__ int hist[NCLS];

    const int tid = threadIdx.x;
    const int warp = tid >> 5, lane = tid & 31;
    const int wm = warp * 64;                 // WM=64, WN=64 (all classes)
    const int bm0 = blockIdx.y * STP_BM;
    const __nv_bfloat16* A = qemb + (size_t)bm0 * DEMB;

    if (tid < NCLS) hist[tid] = 0;

    float acc[4][8][4];
#pragma unroll
    for (int i = 0; i < 4; i++)
#pragma unroll
        for (int j = 0; j < 8; j++)
#pragma unroll
            for (int q = 0; q < 4; q++) acc[i][j][q] = 0.f;

    const int KT = DEMB >> 6;  // 16

    auto load = [&](int kt) {
        uint32_t sA = sbase + (kt % 3) * STP_STAGE;
        uint32_t sB = sA + (uint32_t)STP_BM * 128u;
        const __nv_bfloat16* Ap = A + (size_t)kt * 64;
        const __nv_bfloat16* Bp = pb + (size_t)kt * 64;
#pragma unroll
        for (int i = 0; i < STP_BM * 8 / 256; i++) {   // 16 iters
            int idx = tid + i * 256;
            int r = idx >> 3, c = idx & 7;
            CP_ASYNC(sA + (uint32_t)(r * 128 + ((c ^ (r & 7)) * 16)), Ap + (size_t)r * DEMB + c * 8);
        }
#pragma unroll
        for (int i = 0; i < 2; i++) {
            int idx = tid + i * 256;
            int r = idx >> 3, c = idx & 7;
            CP_ASYNC(sB + (uint32_t)(r * 128 + ((c ^ (r & 7)) * 16)), Bp + (size_t)r * DEMB + c * 8);
        }
        asm volatile("cp.async.commit_group;\n");
    };

    load(0);
    load(1);
    for (int kt = 0; kt < KT; kt++) {
        if (kt < KT - 1)
            asm volatile("cp.async.wait_group 1;\n" ::: "memory");
        else
            asm volatile("cp.async.wait_group 0;\n" ::: "memory");
        __syncthreads();
        if (kt + 2 < KT) load(kt + 2);
        uint32_t aBase = sbase + (kt % 3) * STP_STAGE;
        uint32_t bBase = aBase + (uint32_t)STP_BM * 128u;
#pragma unroll
        for (int ks = 0; ks < 4; ks++) {
            uint32_t af[4][4];
#pragma unroll
            for (int mi = 0; mi < 4; mi++) {
                int row = wm + mi * 16 + (lane & 15);
                int ch = (ks * 2 + (lane >> 4)) ^ (row & 7);
                uint32_t adr = aBase + (uint32_t)(row * 128 + ch * 16);
                asm volatile("ldmatrix.sync.aligned.m8n8.x4.shared.b16 {%0,%1,%2,%3},[%4];"
                             : "=r"(af[mi][0]), "=r"(af[mi][1]), "=r"(af[mi][2]), "=r"(af[mi][3])
                             : "r"(adr));
            }
            uint32_t bfr[8][2];
#pragma unroll
            for (int ni2 = 0; ni2 < 4; ni2++) {
                int nrow = ni2 * 16 + (lane & 7) + ((lane >> 4) << 3);
                int ch = (ks * 2 + ((lane >> 3) & 1)) ^ (nrow & 7);
                uint32_t bd = bBase + (uint32_t)(nrow * 128 + ch * 16);
                uint32_t r0, r1, r2, r3;
                asm volatile("ldmatrix.sync.aligned.m8n8.x4.shared.b16 {%0,%1,%2,%3},[%4];"
                             : "=r"(r0), "=r"(r1), "=r"(r2), "=r"(r3)
                             : "r"(bd));
                bfr[2 * ni2][0] = r0; bfr[2 * ni2][1] = r1;
                bfr[2 * ni2 + 1][0] = r2; bfr[2 * ni2 + 1][1] = r3;
            }
#pragma unroll
            for (int mi = 0; mi < 4; mi++)
#pragma unroll
                for (int ni = 0; ni < 8; ni++)
                    asm volatile(
                        "mma.sync.aligned.m16n8k16.row.col.f32.bf16.bf16.f32 "
                        "{%0,%1,%2,%3},{%4,%5,%6,%7},{%8,%9},{%0,%1,%2,%3};"
                        : "+f"(acc[mi][ni][0]), "+f"(acc[mi][ni][1]),
                          "+f"(acc[mi][ni][2]), "+f"(acc[mi][ni][3])
                        : "r"(af[mi][0]), "r"(af[mi][1]), "r"(af[mi][2]), "r"(af[mi][3]),
                          "r"(bfr[ni][0]), "r"(bfr[ni][1]));
        }
    }

    // argmin over 64 classes (margin = pnorm - 2*dot), tie -> lowest index
    {
        float bv[4][2];
        int bc[4][2];
#pragma unroll
        for (int mi = 0; mi < 4; mi++)
#pragma unroll
            for (int h = 0; h < 2; h++) { bv[mi][h] = 1e30f; bc[mi][h] = 0; }
#pragma unroll
        for (int ni = 0; ni < 8; ni++)
#pragma unroll
            for (int j = 0; j < 2; j++) {
                int c = ni * 8 + (lane & 3) * 2 + j;
                float pn = __ldg(&pnorm[c]);
#pragma unroll
                for (int mi = 0; mi < 4; mi++)
#pragma unroll
                    for (int h = 0; h < 2; h++) {
                        float m = pn - 2.f * acc[mi][ni][2 * h + j];
                        if (m < bv[mi][h]) { bv[mi][h] = m; bc[mi][h] = c; }
                    }
            }
#pragma unroll
        for (int off = 1; off <= 2; off <<= 1)
#pragma unroll
            for (int mi = 0; mi < 4; mi++)
#pragma unroll
                for (int h = 0; h < 2; h++) {
                    float ov = __shfl_xor_sync(~0u, bv[mi][h], off);
                    int oc = __shfl_xor_sync(~0u, bc[mi][h], off);
                    if (ov < bv[mi][h] || (ov == bv[mi][h] && oc < bc[mi][h])) {
                        bv[mi][h] = ov; bc[mi][h] = oc;
                    }
                }
        if ((lane & 3) == 0) {
#pragma unroll
            for (int mi = 0; mi < 4; mi++)
#pragma unroll
                for (int h = 0; h < 2; h++) {
                    int row = wm + mi * 16 + (lane >> 2) + 8 * h;
                    labels_s[row] = (short)bc[mi][h];
                    atomicAdd(&hist[bc[mi][h]], 1);
                }
        }
    }
    __syncthreads();
    if (tid < NCLS) atomicAdd(&qcount[tid], (float)hist[tid]);

    // ---- Phase B: per-class accumulate of own 512 rows ----
    // bins[rg][cls][cp]: 4 row-groups (128 rows each) x 64 classes x 64 float2 = 128KB
    float2* bins = (float2*)smem_raw;
    float4* bins4 = (float4*)smem_raw;   // [rg][cls][32 float4]
    const int rg = tid >> 6;        // 0..3 (rows rg*128 .. rg*128+127)
    const int cp = tid & 63;        // bf162 column within 64-pair chunk
    const __nv_bfloat162* q2 = (const __nv_bfloat162*)(qemb) + (size_t)bm0 * 512;
    for (int i = tid; i < 4 * NCLS * 64; i += 256) {
        bins[i].x = 0.f; bins[i].y = 0.f;
    }
    __syncthreads();
#pragma unroll 1
    for (int chunk = 0; chunk < 8; chunk++) {
        float2* mybins = bins + rg * NCLS * 64 + cp;
#pragma unroll 4
        for (int r = 0; r < 128; r++) {
            int row = rg * 128 + r;
            int L = labels_s[row];
            float2 v = __bfloat1622float2(q2[(size_t)row * 512 + chunk * 64 + cp]);
            float2* b = mybins + L * 64;
            b->x += v.x; b->y += v.y;
        }
        __syncthreads();
        const float4 z4 = make_float4(0.f, 0.f, 0.f, 0.f);
        for (int i = tid; i < NCLS * 32; i += 256) {
            int cls = i >> 5, c4 = i & 31;
            float4 s0 = bins4[(0 * NCLS + cls) * 32 + c4];
            float4 s1 = bins4[(1 * NCLS + cls) * 32 + c4];
            float4 s2 = bins4[(2 * NCLS + cls) * 32 + c4];
            float4 s3 = bins4[(3 * NCLS + cls) * 32 + c4];
            bins4[(0 * NCLS + cls) * 32 + c4] = z4;
            bins4[(1 * NCLS + cls) * 32 + c4] = z4;
            bins4[(2 * NCLS + cls) * 32 + c4] = z4;
            bins4[(3 * NCLS + cls) * 32 + c4] = z4;
            float4 v;
            v.x = s0.x + s1.x + s2.x + s3.x;
            v.y = s0.y + s1.y + s2.y + s3.y;
            v.z = s0.z + s1.z + s2.z + s3.z;
            v.w = s0.w + s1.w + s2.w + s3.w;
            RED_V4(&qsum[cls * DEMB + chunk * 128 + c4 * 4], v);
        }
        __syncthreads();
    }
}

// ---------------- bf16 HMMA GEMM (embedding + logits) ----------------
// MODE 0: merged embedding GEMM (query + support), bias fused, qnorm accumulated
// MODE 2: outf[m*NCLS+n] = -sqrt(max(qnorm[m]+pnorm[n]-2*C, 1e-12))
template <int BM, int BN, int WMT, int WNT, int MODE>
__global__ void __launch_bounds__(WMT* WNT * 32, 1) k_gemm(
    const __nv_bfloat16* __restrict__ A, const __nv_bfloat16* __restrict__ B, int K,
    const float* __restrict__ bias, __nv_bfloat16* __restrict__ outb, int ldo,
    const float* __restrict__ pnorm, float* __restrict__ qnorm, float* __restrict__ outf,
    const __nv_bfloat16* __restrict__ A2, __nv_bfloat16* __restrict__ outb2, int nqy) {
    constexpr int NT = WMT * WNT * 32;
    constexpr int WM = BM / WMT, WN = BN / WNT;
    constexpr int MF = WM / 16, NF = WN / 8;
    constexpr int AIT = BM * 8 / NT;
    constexpr int BIT = BN * 8 / NT;
    constexpr uint32_t STAGE = (BM + BN) * 128;

    extern __shared__ char smem_raw[];
    uint32_t sbase = (uint32_t)__cvta_generic_to_shared(smem_raw);

    const int tid = threadIdx.x;
    const int warp = tid >> 5, lane = tid & 31;
    const int wm = (warp / WNT) * WM, wn = (warp % WNT) * WN;
    const int bn0 = blockIdx.x * BN;

    bool isq = true;
    int ybase = blockIdx.y;
    const __nv_bfloat16* Asel = A;
    __nv_bfloat16* osel = outb;
    if (MODE == 0 && (int)blockIdx.y >= nqy) {
        isq = false;
        ybase = blockIdx.y - nqy;
        Asel = A2;
        osel = outb2;
    }
    const int bm0 = ybase * BM;

    const __nv_bfloat16* Ab = Asel + (size_t)bm0 * K;
    const __nv_bfloat16* Bb = B + (size_t)bn0 * K;

    float acc[MF][NF][4];
#pragma unroll
    for (int i = 0; i < MF; i++)
#pragma unroll
        for (int j = 0; j < NF; j++)
#pragma unroll
            for (int q = 0; q < 4; q++) acc[i][j][q] = 0.f;

    const int KT = K >> 6;

    auto load = [&](int kt) {
        uint32_t sA = sbase + (kt % 3) * STAGE;
        uint32_t sB = sA + (uint32_t)BM * 128u;
        const __nv_bfloat16* Ap = Ab + (size_t)kt * 64;
        const __nv_bfloat16* Bp = Bb + (size_t)kt * 64;
#pragma unroll
        for (int i = 0; i < AIT; i++) {
            int idx = tid + i * NT;
            int r = idx >> 3, c = idx & 7;
            CP_ASYNC(sA + (uint32_t)(r * 128 + ((c ^ (r & 7)) * 16)), Ap + (size_t)r * K + c * 8);
        }
#pragma unroll
        for (int i = 0; i < BIT; i++) {
            int idx = tid + i * NT;
            int r = idx >> 3, c = idx & 7;
            CP_ASYNC(sB + (uint32_t)(r * 128 + ((c ^ (r & 7)) * 16)), Bp + (size_t)r * K + c * 8);
        }
        asm volatile("cp.async.commit_group;\n");
    };

    load(0);
    load(1);
    for (int kt = 0; kt < KT; kt++) {
        if (kt < KT - 1)
            asm volatile("cp.async.wait_group 1;\n" ::: "memory");
        else
            asm volatile("cp.async.wait_group 0;\n" ::: "memory");
        __syncthreads();
        if (kt + 2 < KT) load(kt + 2);
        uint32_t aBase = sbase + (kt % 3) * STAGE;
        uint32_t bBase = aBase + (uint32_t)BM * 128u;
#pragma unroll
        for (int ks = 0; ks < 4; ks++) {
            uint32_t af[MF][4];
#pragma unroll
            for (int mi = 0; mi < MF; mi++) {
                int row = wm + mi * 16 + (lane & 15);
                int ch = (ks * 2 + (lane >> 4)) ^ (row & 7);
                uint32_t adr = aBase + (uint32_t)(row * 128 + ch * 16);
                asm volatile("ldmatrix.sync.aligned.m8n8.x4.shared.b16 {%0,%1,%2,%3},[%4];"
                             : "=r"(af[mi][0]), "=r"(af[mi][1]), "=r"(af[mi][2]), "=r"(af[mi][3])
                             : "r"(adr));
            }
            uint32_t bfr[NF][2];
#pragma unroll
            for (int ni2 = 0; ni2 < NF / 2; ni2++) {
                int nrow = wn + ni2 * 16 + (lane & 7) + ((lane >> 4) << 3);
                int ch = (ks * 2 + ((lane >> 3) & 1)) ^ (nrow & 7);
                uint32_t bd = bBase + (uint32_t)(nrow * 128 + ch * 16);
                uint32_t r0, r1, r2, r3;
                asm volatile("ldmatrix.sync.aligned.m8n8.x4.shared.b16 {%0,%1,%2,%3},[%4];"
                             : "=r"(r0), "=r"(r1), "=r"(r2), "=r"(r3)
                             : "r"(bd));
                bfr[2 * ni2][0] = r0; bfr[2 * ni2][1] = r1;
                bfr[2 * ni2 + 1][0] = r2; bfr[2 * ni2 + 1][1] = r3;
            }
#pragma unroll
            for (int mi = 0; mi < MF; mi++)
#pragma unroll
                for (int ni = 0; ni < NF; ni++)
                    asm volatile(
                        "mma.sync.aligned.m16n8k16.row.col.f32.bf16.bf16.f32 "
                        "{%0,%1,%2,%3},{%4,%5,%6,%7},{%8,%9},{%0,%1,%2,%3};"
                        : "+f"(acc[mi][ni][0]), "+f"(acc[mi][ni][1]),
                          "+f"(acc[mi][ni][2]), "+f"(acc[mi][ni][3])
                        : "r"(af[mi][0]), "r"(af[mi][1]), "r"(af[mi][2]), "r"(af[mi][3]),
                          "r"(bfr[ni][0]), "r"(bfr[ni][1]));
        }
    }

    if (MODE == 0) {
#pragma unroll
        for (int mi = 0; mi < MF; mi++) {
            int row = bm0 + wm + mi * 16 + (lane >> 2);
#pragma unroll
            for (int h = 0; h < 2; h++) {
                int rr = row + h * 8;
                float rs = 0.f;
#pragma unroll
                for (int ni = 0; ni < NF; ni++) {
                    int col = bn0 + wn + ni * 8 + (lane & 3) * 2;
                    float b0v = __ldg(&bias[col]), b1v = __ldg(&bias[col + 1]);
                    __nv_bfloat162 p = __floats2bfloat162_rn(acc[mi][ni][2 * h] + b0v,
                                                             acc[mi][ni][2 * h + 1] + b1v);
                    *(__nv_bfloat162*)(osel + (size_t)rr * ldo + col) = p;
                    float x = __bfloat162float(p.x), y = __bfloat162float(p.y);
                    rs += x * x + y * y;
                }
                if (isq) {
                    rs += __shfl_xor_sync(~0u, rs, 1);
                    rs += __shfl_xor_sync(~0u, rs, 2);
                    if ((lane & 3) == 0) atomicAdd(&qnorm[rr], rs);
                }
            }
        }
    } else {  // MODE 2
#pragma unroll
        for (int mi = 0; mi < MF; mi++) {
            int row = bm0 + wm + mi * 16 + (lane >> 2);
#pragma unroll
            for (int h = 0; h < 2; h++) {
                int rr = row + 8 * h;
                float qn = __ldg(&qnorm[rr]);
#pragma unroll
                for (int ni = 0; ni < NF; ni++)
#pragma unroll
                    for (int j = 0; j < 2; j++) {
                        int c = wn + ni * 8 + (lane & 3) * 2 + j;
                        float d2 = qn + __ldg(&pnorm[c]) - 2.f * acc[mi][ni][2 * h + j];
                        outf[(size_t)rr * NCLS + c] = -sqrtf(fmaxf(d2, 1e-12f));
                    }
            }
        }
    }
}

// ---------------- host orchestration ----------------
extern "C" void kernel_launch(void* const* d_in, const int* in_sizes, int n_in,
                              void* d_out, int out_size) {
    (void)in_sizes; (void)n_in; (void)out_size;
    const float* support = (const float*)d_in[0];
    const float* query = (const float*)d_in[1];
    const int* slab = (const int*)d_in[2];
    const float* W = (const float*)d_in[3];
    const float* bias = (const float*)d_in[4];
    float* out = (float*)d_out;

    __nv_bfloat16 *Wt, *qx, *sx, *qemb, *semb, *pb;
    float *qnorm, *ssum, *scount, *qsum, *qcount, *pnorm;
    cudaGetSymbolAddress((void**)&Wt, g_Wt);
    cudaGetSymbolAddress((void**)&qx, g_qx);
    cudaGetSymbolAddress((void**)&sx, g_sx);
    cudaGetSymbolAddress((void**)&qemb, g_qemb);
    cudaGetSymbolAddress((void**)&semb, g_semb);
    cudaGetSymbolAddress((void**)&qnorm, g_qnorm);
    cudaGetSymbolAddress((void**)&ssum, g_ssum);
    cudaGetSymbolAddress((void**)&scount, g_scount);
    cudaGetSymbolAddress((void**)&qsum, g_qsum);
    cudaGetSymbolAddress((void**)&qcount, g_qcount);
    cudaGetSymbolAddress((void**)&pb, g_pb);
    cudaGetSymbolAddress((void**)&pnorm, g_pnorm);

    const int SMEM_BIG = 3 * (128 + 256) * 128;   // 147456
    const int SMEM_SML = 3 * (128 + 64) * 128;    // 73728
    cudaFuncSetAttribute(k_gemm<128, 256, 2, 4, 0>, cudaFuncAttributeMaxDynamicSharedMemorySize, SMEM_BIG);
    cudaFuncSetAttribute(k_gemm<128, 64, 4, 2, 2>, cudaFuncAttributeMaxDynamicSharedMemorySize, SMEM_SML);
    cudaFuncSetAttribute(k_step, cudaFuncAttributeMaxDynamicSharedMemorySize, STP_SMEM);

    // launch order: profiler captures the 4th launch = merged big GEMM
    k_convert<<<(NQRY * DIN / 4 + 255) / 256, 256>>>(query, qx, NQRY * DIN / 4);
    k_convert<<<(NSUP * DIN / 4 + 255) / 256, 256>>>(support, sx, NSUP * DIN / 4);
    k_transpose_w<<<dim3(DEMB / 32, DIN / 32), dim3(32, 8)>>>(W, Wt, qnorm, ssum, scount);

    // merged embedding GEMM (query y-blocks [0,512), support [512,522)), 256 threads
    k_gemm<128, 256, 2, 4, 0><<<dim3(DEMB / 256, QYB + NSUP / 128), 256, SMEM_BIG>>>(
        qx, Wt, DIN, bias, qemb, DEMB, nullptr, qnorm, nullptr, sx, semb, QYB);

    // support class sums + counts -> initial prototypes (also zeroes qsum/qcount)
    k_supp_stats<<<NSUP, 256>>>(semb, slab, ssum, scount);
    k_proto<<<NCLS, 256>>>(ssum, scount, qsum, qcount, 0, pb, pnorm);

    for (int s = 0; s < NSTEPS; s++) {
        k_step<<<dim3(1, NQRY / STP_BM), 256, STP_SMEM>>>(qemb, pb, pnorm, qsum, qcount);
        k_proto<<<NCLS, 256>>>(ssum, scount, qsum, qcount, 1, pb, pnorm);
    }

    // final logits
    k_gemm<128, 64, 4, 2, 2><<<dim3(1, NQRY / 128), 256, SMEM_SML>>>(
        qemb, pb, DEMB, nullptr, nullptr, 0, pnorm, qnorm, out, nullptr, nullptr, 1 << 20);
}

// round 12
// speedup vs baseline: 1.3600x; 1.3600x over previous
#include <cuda_runtime.h>
#include <cuda_bf16.h>
#include <stdint.h>

#define NSUP   1280
#define NQRY   65536
#define DIN    2048
#define DEMB   1024
#define NCLS   64
#define NSTEPS 5
#define QYB    (NQRY / 128)   // 512 query y-blocks

// ---------------- scratch (device globals; no allocation) ----------------
__device__ __align__(256) __nv_bfloat16 g_Wt[(size_t)DEMB * DIN];      // [DEMB][DIN]
__device__ __align__(256) __nv_bfloat16 g_qx[(size_t)NQRY * DIN];
__device__ __align__(256) __nv_bfloat16 g_sx[(size_t)NSUP * DIN];
__device__ __align__(256) __nv_bfloat16 g_qemb[(size_t)NQRY * DEMB];
__device__ __align__(256) __nv_bfloat16 g_semb[(size_t)NSUP * DEMB];
__device__ float g_qnorm[NQRY];
__device__ float g_ssum[NCLS * DEMB];
__device__ float g_scount[NCLS];
__device__ __align__(16) float g_qsum[NCLS * DEMB];
__device__ float g_qcount[NCLS];
__device__ __align__(256) __nv_bfloat16 g_pb[NCLS * DEMB];             // prototypes bf16
__device__ float g_pnorm[NCLS];

#define CP_ASYNC(dst, src) asm volatile("cp.async.cg.shared.global [%0], [%1], 16;\n" ::"r"(dst), "l"(src))
#define RED_V4(ptr, v) \
    asm volatile("red.global.add.v4.f32 [%0], {%1,%2,%3,%4};" \
                 ::"l"(ptr), "f"((v).x), "f"((v).y), "f"((v).z), "f"((v).w) : "memory")

// ---------------- fused prep: converts + W transpose + qnorm zero ----------------
// grid ranges: [0,QB) convert query; [QB,QB+SB) convert support; [QB+SB, +2048) transpose W.
#define QB_PREP (NQRY * DIN / 4 / 256)   // 131072
#define SB_PREP (NSUP * DIN / 4 / 256)   // 2560
#define TB_PREP (DIN / 32 * DEMB / 32)   // 2048

__global__ void __launch_bounds__(256) k_prep(
    const float* __restrict__ query, const float* __restrict__ support,
    const float* __restrict__ W, __nv_bfloat16* __restrict__ qx,
    __nv_bfloat16* __restrict__ sx, __nv_bfloat16* __restrict__ Wt,
    float* __restrict__ qnorm) {
    __shared__ float tile[32][33];
    int b = blockIdx.x;
    int tid = threadIdx.x;
    if (b < QB_PREP + SB_PREP) {
        const float* src = (b < QB_PREP) ? query : support;
        __nv_bfloat16* dst = (b < QB_PREP) ? qx : sx;
        int i = (b < QB_PREP ? b : b - QB_PREP) * 256 + tid;
        float4 v = ((const float4*)src)[i];
        ((__nv_bfloat162*)dst)[2 * i + 0] = __floats2bfloat162_rn(v.x, v.y);
        ((__nv_bfloat162*)dst)[2 * i + 1] = __floats2bfloat162_rn(v.z, v.w);
    } else {
        int tb = b - QB_PREP - SB_PREP;          // 0..2047
        int n0 = (tb & 31) * 32;                 // DEMB/32 = 32
        int k0 = (tb >> 5) * 32;                 // DIN/32 = 64
        int tx = tid & 31, ty = tid >> 5;        // 32 x 8
#pragma unroll
        for (int i = 0; i < 4; i++) {
            int k = k0 + ty + i * 8;
            tile[ty + i * 8][tx] = W[(size_t)k * DEMB + n0 + tx];
        }
        if (tid < 32) qnorm[tb * 32 + tid] = 0.f;
        __syncthreads();
#pragma unroll
        for (int i = 0; i < 4; i++) {
            int n = n0 + ty + i * 8;
            Wt[(size_t)n * DIN + k0 + tx] = __float2bfloat16(tile[tx][ty + i * 8]);
        }
    }
}

// ---------------- fused support stats + initial prototypes ----------------
// block c: scan labels (smem), sum class-c support rows (4 cols/thread),
// write ssum/scount (for in-loop protos), pb/pnorm; zero qsum/qcount.
__global__ void __launch_bounds__(256) k_supp_proto(
    const __nv_bfloat16* __restrict__ semb, const int* __restrict__ lab,
    float* __restrict__ ssum, float* __restrict__ scount,
    float* __restrict__ qsum, float* __restrict__ qcount,
    __nv_bfloat16* __restrict__ pb, float* __restrict__ pnorm) {
    int c = blockIdx.x;
    int tid = threadIdx.x;
    __shared__ short labs[NSUP];
    for (int i = tid; i < NSUP; i += 256) labs[i] = (short)__ldg(&lab[i]);
    __syncthreads();
    float a0 = 0.f, a1 = 0.f, a2 = 0.f, a3 = 0.f;
    int cnt = 0;
    for (int r = 0; r < NSUP; r++) {
        if (labs[r] == c) {
            cnt++;
            const __nv_bfloat16* row = semb + (size_t)r * DEMB + tid * 4;
            __nv_bfloat162 v0 = *(const __nv_bfloat162*)(row);
            __nv_bfloat162 v1 = *(const __nv_bfloat162*)(row + 2);
            float2 f0 = __bfloat1622float2(v0), f1 = __bfloat1622float2(v1);
            a0 += f0.x; a1 += f0.y; a2 += f1.x; a3 += f1.y;
        }
    }
    float inv = 1.f / fmaxf((float)cnt, 1.f);
    int j = c * DEMB + tid * 4;
    ssum[j] = a0; ssum[j + 1] = a1; ssum[j + 2] = a2; ssum[j + 3] = a3;
    qsum[j] = 0.f; qsum[j + 1] = 0.f; qsum[j + 2] = 0.f; qsum[j + 3] = 0.f;
    __nv_bfloat16 p0 = __float2bfloat16(a0 * inv), p1 = __float2bfloat16(a1 * inv);
    __nv_bfloat16 p2 = __float2bfloat16(a2 * inv), p3 = __float2bfloat16(a3 * inv);
    pb[j] = p0; pb[j + 1] = p1; pb[j + 2] = p2; pb[j + 3] = p3;
    float f0 = __bfloat162float(p0), f1 = __bfloat162float(p1);
    float f2 = __bfloat162float(p2), f3 = __bfloat162float(p3);
    float s = f0 * f0 + f1 * f1 + f2 * f2 + f3 * f3;
    __shared__ float red[8];
#pragma unroll
    for (int o2 = 16; o2; o2 >>= 1) s += __shfl_xor_sync(~0u, s, o2);
    if ((tid & 31) == 0) red[tid >> 5] = s;
    __syncthreads();
    if (tid < 8) {
        s = red[tid];
#pragma unroll
        for (int o2 = 4; o2; o2 >>= 1) s += __shfl_xor_sync(0xff, s, o2);
        if (tid == 0) {
            pnorm[c] = s;
            scount[c] = (float)cnt;
            qcount[c] = 0.f;
        }
    }
}

// prototypes from (ssum + qsum) / counts; ALSO zeroes qsum/qcount for the next pass.
__global__ void k_proto(const float* __restrict__ ssum, const float* __restrict__ scount,
                        float* __restrict__ qsum, float* __restrict__ qcount,
                        __nv_bfloat16* __restrict__ pb, float* __restrict__ pnorm) {
    int c = blockIdx.x;
    float cnt = scount[c] + qcount[c];
    float inv = 1.f / fmaxf(cnt, 1.f);
    float s = 0.f;
    for (int j = threadIdx.x; j < DEMB; j += blockDim.x) {
        float p = (ssum[c * DEMB + j] + qsum[c * DEMB + j]) * inv;
        qsum[c * DEMB + j] = 0.f;
        __nv_bfloat16 pv = __float2bfloat16(p);
        pb[c * DEMB + j] = pv;
        float pf = __bfloat162float(pv);
        s += pf * pf;
    }
    if (threadIdx.x == 0) qcount[c] = 0.f;
    __shared__ float red[8];
#pragma unroll
    for (int o2 = 16; o2; o2 >>= 1) s += __shfl_xor_sync(~0u, s, o2);
    if ((threadIdx.x & 31) == 0) red[threadIdx.x >> 5] = s;
    __syncthreads();
    if (threadIdx.x < 8) {
        s = red[threadIdx.x];
#pragma unroll
        for (int o2 = 4; o2; o2 >>= 1) s += __shfl_xor_sync(0xff, s, o2);
        if (threadIdx.x == 0) pnorm[c] = s;
    }
}

// ================= fused transductive step (R8 exact — best known) =================
#define STP_STAGE ((256 + 64) * 128)   // 40960 B per stage (A 32KB + B 8KB)
#define STP_SMEM  131072

__global__ void __launch_bounds__(256, 1) k_step(
    const __nv_bfloat16* __restrict__ qemb, const __nv_bfloat16* __restrict__ pb,
    const float* __restrict__ pnorm, float* __restrict__ qsum, float* __restrict__ qcount) {
    extern __shared__ char smem_raw[];
    uint32_t sbase = (uint32_t)__cvta_generic_to_shared(smem_raw);
    __shared__ short labels_s[256];
    __shared__ int hist[NCLS];

    const int tid = threadIdx.x;
    const int warp = tid >> 5, lane = tid & 31;
    const int wm = warp * 32;                 // WM=32, WN=64 (all classes)
    const int bm0 = blockIdx.y * 256;
    const __nv_bfloat16* A = qemb + (size_t)bm0 * DEMB;

    if (tid < NCLS) hist[tid] = 0;

    float acc[2][8][4];
#pragma unroll
    for (int i = 0; i < 2; i++)
#pragma unroll
        for (int j = 0; j < 8; j++)
#pragma unroll
            for (int q = 0; q < 4; q++) acc[i][j][q] = 0.f;

    const int KT = DEMB >> 6;  // 16

    auto load = [&](int kt) {
        uint32_t sA = sbase + (kt % 3) * STP_STAGE;
        uint32_t sB = sA + 256u * 128u;
        const __nv_bfloat16* Ap = A + (size_t)kt * 64;
        const __nv_bfloat16* Bp = pb + (size_t)kt * 64;
#pragma unroll
        for (int i = 0; i < 8; i++) {
            int idx = tid + i * 256;
            int r = idx >> 3, c = idx & 7;
            CP_ASYNC(sA + (uint32_t)(r * 128 + ((c ^ (r & 7)) * 16)), Ap + (size_t)r * DEMB + c * 8);
        }
#pragma unroll
        for (int i = 0; i < 2; i++) {
            int idx = tid + i * 256;
            int r = idx >> 3, c = idx & 7;
            CP_ASYNC(sB + (uint32_t)(r * 128 + ((c ^ (r & 7)) * 16)), Bp + (size_t)r * DEMB + c * 8);
        }
        asm volatile("cp.async.commit_group;\n");
    };

    load(0);
    load(1);
    for (int kt = 0; kt < KT; kt++) {
        if (kt < KT - 1)
            asm volatile("cp.async.wait_group 1;\n" ::: "memory");
        else
            asm volatile("cp.async.wait_group 0;\n" ::: "memory");
        __syncthreads();
        if (kt + 2 < KT) load(kt + 2);
        uint32_t aBase = sbase + (kt % 3) * STP_STAGE;
        uint32_t bBase = aBase + 256u * 128u;
#pragma unroll
        for (int ks = 0; ks < 4; ks++) {
            uint32_t af[2][4];
#pragma unroll
            for (int mi = 0; mi < 2; mi++) {
                int row = wm + mi * 16 + (lane & 15);
                int ch = (ks * 2 + (lane >> 4)) ^ (row & 7);
                uint32_t adr = aBase + (uint32_t)(row * 128 + ch * 16);
                asm volatile("ldmatrix.sync.aligned.m8n8.x4.shared.b16 {%0,%1,%2,%3},[%4];"
                             : "=r"(af[mi][0]), "=r"(af[mi][1]), "=r"(af[mi][2]), "=r"(af[mi][3])
                             : "r"(adr));
            }
            uint32_t bfr[8][2];
#pragma unroll
            for (int ni2 = 0; ni2 < 4; ni2++) {
                int nrow = ni2 * 16 + (lane & 7) + ((lane >> 4) << 3);
                int ch = (ks * 2 + ((lane >> 3) & 1)) ^ (nrow & 7);
                uint32_t bd = bBase + (uint32_t)(nrow * 128 + ch * 16);
                uint32_t r0, r1, r2, r3;
                asm volatile("ldmatrix.sync.aligned.m8n8.x4.shared.b16 {%0,%1,%2,%3},[%4];"
                             : "=r"(r0), "=r"(r1), "=r"(r2), "=r"(r3)
                             : "r"(bd));
                bfr[2 * ni2][0] = r0; bfr[2 * ni2][1] = r1;
                bfr[2 * ni2 + 1][0] = r2; bfr[2 * ni2 + 1][1] = r3;
            }
#pragma unroll
            for (int mi = 0; mi < 2; mi++)
#pragma unroll
                for (int ni = 0; ni < 8; ni++)
                    asm volatile(
                        "mma.sync.aligned.m16n8k16.row.col.f32.bf16.bf16.f32 "
                        "{%0,%1,%2,%3},{%4,%5,%6,%7},{%8,%9},{%0,%1,%2,%3};"
                        : "+f"(acc[mi][ni][0]), "+f"(acc[mi][ni][1]),
                          "+f"(acc[mi][ni][2]), "+f"(acc[mi][ni][3])
                        : "r"(af[mi][0]), "r"(af[mi][1]), "r"(af[mi][2]), "r"(af[mi][3]),
                          "r"(bfr[ni][0]), "r"(bfr[ni][1]));
        }
    }

    // argmin over 64 classes (margin = pnorm - 2*dot), tie -> lowest index
    {
        float bv[2][2];
        int bc[2][2];
#pragma unroll
        for (int mi = 0; mi < 2; mi++)
#pragma unroll
            for (int h = 0; h < 2; h++) { bv[mi][h] = 1e30f; bc[mi][h] = 0; }
#pragma unroll
        for (int ni = 0; ni < 8; ni++)
#pragma unroll
            for (int j = 0; j < 2; j++) {
                int c = ni * 8 + (lane & 3) * 2 + j;
                float pn = __ldg(&pnorm[c]);
#pragma unroll
                for (int mi = 0; mi < 2; mi++)
#pragma unroll
                    for (int h = 0; h < 2; h++) {
                        float m = pn - 2.f * acc[mi][ni][2 * h + j];
                        if (m < bv[mi][h]) { bv[mi][h] = m; bc[mi][h] = c; }
                    }
            }
#pragma unroll
        for (int off = 1; off <= 2; off <<= 1)
#pragma unroll
            for (int mi = 0; mi < 2; mi++)
#pragma unroll
                for (int h = 0; h < 2; h++) {
                    float ov = __shfl_xor_sync(~0u, bv[mi][h], off);
                    int oc = __shfl_xor_sync(~0u, bc[mi][h], off);
                    if (ov < bv[mi][h] || (ov == bv[mi][h] && oc < bc[mi][h])) {
                        bv[mi][h] = ov; bc[mi][h] = oc;
                    }
                }
        if ((lane & 3) == 0) {
#pragma unroll
            for (int mi = 0; mi < 2; mi++)
#pragma unroll
                for (int h = 0; h < 2; h++) {
                    int row = wm + mi * 16 + (lane >> 2) + 8 * h;
                    labels_s[row] = (short)bc[mi][h];
                    atomicAdd(&hist[bc[mi][h]], 1);
                }
        }
    }
    __syncthreads();
    if (tid < NCLS) atomicAdd(&qcount[tid], (float)hist[tid]);

    // ---- Phase B: per-class accumulate of own 256 rows ----
    float2* bins = (float2*)smem_raw;
    float4* bins4 = (float4*)smem_raw;   // [rg][cls][32 float4]
    const int rg = tid >> 6;
    const int cp = tid & 63;
    const __nv_bfloat162* q2 = (const __nv_bfloat162*)(qemb) + (size_t)bm0 * 512;
    for (int i = tid; i < 4 * NCLS * 64; i += 256) {
        bins[i].x = 0.f; bins[i].y = 0.f;
    }
    __syncthreads();
#pragma unroll 1
    for (int chunk = 0; chunk < 8; chunk++) {
        float2* mybins = bins + rg * NCLS * 64 + cp;
#pragma unroll 4
        for (int r = 0; r < 64; r++) {
            int row = rg * 64 + r;
            int L = labels_s[row];
            float2 v = __bfloat1622float2(q2[(size_t)row * 512 + chunk * 64 + cp]);
            float2* b = mybins + L * 64;
            b->x += v.x; b->y += v.y;
        }
        __syncthreads();
        const float4 z4 = make_float4(0.f, 0.f, 0.f, 0.f);
        for (int i = tid; i < NCLS * 32; i += 256) {
            int cls = i >> 5, c4 = i & 31;
            float4 s0 = bins4[(0 * NCLS + cls) * 32 + c4];
            float4 s1 = bins4[(1 * NCLS + cls) * 32 + c4];
            float4 s2 = bins4[(2 * NCLS + cls) * 32 + c4];
            float4 s3 = bins4[(3 * NCLS + cls) * 32 + c4];
            bins4[(0 * NCLS + cls) * 32 + c4] = z4;
            bins4[(1 * NCLS + cls) * 32 + c4] = z4;
            bins4[(2 * NCLS + cls) * 32 + c4] = z4;
            bins4[(3 * NCLS + cls) * 32 + c4] = z4;
            float4 v;
            v.x = s0.x + s1.x + s2.x + s3.x;
            v.y = s0.y + s1.y + s2.y + s3.y;
            v.z = s0.z + s1.z + s2.z + s3.z;
            v.w = s0.w + s1.w + s2.w + s3.w;
            RED_V4(&qsum[cls * DEMB + chunk * 128 + c4 * 4], v);
        }
        __syncthreads();
    }
}

// ---------------- bf16 HMMA GEMM (embedding + logits) ----------------
template <int BM, int BN, int WMT, int WNT, int MODE>
__global__ void __launch_bounds__(WMT* WNT * 32, 1) k_gemm(
    const __nv_bfloat16* __restrict__ A, const __nv_bfloat16* __restrict__ B, int K,
    const float* __restrict__ bias, __nv_bfloat16* __restrict__ outb, int ldo,
    const float* __restrict__ pnorm, float* __restrict__ qnorm, float* __restrict__ outf,
    const __nv_bfloat16* __restrict__ A2, __nv_bfloat16* __restrict__ outb2, int nqy) {
    constexpr int NT = WMT * WNT * 32;
    constexpr int WM = BM / WMT, WN = BN / WNT;
    constexpr int MF = WM / 16, NF = WN / 8;
    constexpr int AIT = BM * 8 / NT;
    constexpr int BIT = BN * 8 / NT;
    constexpr uint32_t STAGE = (BM + BN) * 128;

    extern __shared__ char smem_raw[];
    uint32_t sbase = (uint32_t)__cvta_generic_to_shared(smem_raw);

    const int tid = threadIdx.x;
    const int warp = tid >> 5, lane = tid & 31;
    const int wm = (warp / WNT) * WM, wn = (warp % WNT) * WN;
    const int bn0 = blockIdx.x * BN;

    bool isq = true;
    int ybase = blockIdx.y;
    const __nv_bfloat16* Asel = A;
    __nv_bfloat16* osel = outb;
    if (MODE == 0 && (int)blockIdx.y >= nqy) {
        isq = false;
        ybase = blockIdx.y - nqy;
        Asel = A2;
        osel = outb2;
    }
    const int bm0 = ybase * BM;

    const __nv_bfloat16* Ab = Asel + (size_t)bm0 * K;
    const __nv_bfloat16* Bb = B + (size_t)bn0 * K;

    float acc[MF][NF][4];
#pragma unroll
    for (int i = 0; i < MF; i++)
#pragma unroll
        for (int j = 0; j < NF; j++)
#pragma unroll
            for (int q = 0; q < 4; q++) acc[i][j][q] = 0.f;

    const int KT = K >> 6;

    auto load = [&](int kt) {
        uint32_t sA = sbase + (kt % 3) * STAGE;
        uint32_t sB = sA + (uint32_t)BM * 128u;
        const __nv_bfloat16* Ap = Ab + (size_t)kt * 64;
        const __nv_bfloat16* Bp = Bb + (size_t)kt * 64;
#pragma unroll
        for (int i = 0; i < AIT; i++) {
            int idx = tid + i * NT;
            int r = idx >> 3, c = idx & 7;
            CP_ASYNC(sA + (uint32_t)(r * 128 + ((c ^ (r & 7)) * 16)), Ap + (size_t)r * K + c * 8);
        }
#pragma unroll
        for (int i = 0; i < BIT; i++) {
            int idx = tid + i * NT;
            int r = idx >> 3, c = idx & 7;
            CP_ASYNC(sB + (uint32_t)(r * 128 + ((c ^ (r & 7)) * 16)), Bp + (size_t)r * K + c * 8);
        }
        asm volatile("cp.async.commit_group;\n");
    };

    load(0);
    load(1);
    for (int kt = 0; kt < KT; kt++) {
        if (kt < KT - 1)
            asm volatile("cp.async.wait_group 1;\n" ::: "memory");
        else
            asm volatile("cp.async.wait_group 0;\n" ::: "memory");
        __syncthreads();
        if (kt + 2 < KT) load(kt + 2);
        uint32_t aBase = sbase + (kt % 3) * STAGE;
        uint32_t bBase = aBase + (uint32_t)BM * 128u;
#pragma unroll
        for (int ks = 0; ks < 4; ks++) {
            uint32_t af[MF][4];
#pragma unroll
            for (int mi = 0; mi < MF; mi++) {
                int row = wm + mi * 16 + (lane & 15);
                int ch = (ks * 2 + (lane >> 4)) ^ (row & 7);
                uint32_t adr = aBase + (uint32_t)(row * 128 + ch * 16);
                asm volatile("ldmatrix.sync.aligned.m8n8.x4.shared.b16 {%0,%1,%2,%3},[%4];"
                             : "=r"(af[mi][0]), "=r"(af[mi][1]), "=r"(af[mi][2]), "=r"(af[mi][3])
                             : "r"(adr));
            }
            uint32_t bfr[NF][2];
#pragma unroll
            for (int ni2 = 0; ni2 < NF / 2; ni2++) {
                int nrow = wn + ni2 * 16 + (lane & 7) + ((lane >> 4) << 3);
                int ch = (ks * 2 + ((lane >> 3) & 1)) ^ (nrow & 7);
                uint32_t bd = bBase + (uint32_t)(nrow * 128 + ch * 16);
                uint32_t r0, r1, r2, r3;
                asm volatile("ldmatrix.sync.aligned.m8n8.x4.shared.b16 {%0,%1,%2,%3},[%4];"
                             : "=r"(r0), "=r"(r1), "=r"(r2), "=r"(r3)
                             : "r"(bd));
                bfr[2 * ni2][0] = r0; bfr[2 * ni2][1] = r1;
                bfr[2 * ni2 + 1][0] = r2; bfr[2 * ni2 + 1][1] = r3;
            }
#pragma unroll
            for (int mi = 0; mi < MF; mi++)
#pragma unroll
                for (int ni = 0; ni < NF; ni++)
                    asm volatile(
                        "mma.sync.aligned.m16n8k16.row.col.f32.bf16.bf16.f32 "
                        "{%0,%1,%2,%3},{%4,%5,%6,%7},{%8,%9},{%0,%1,%2,%3};"
                        : "+f"(acc[mi][ni][0]), "+f"(acc[mi][ni][1]),
                          "+f"(acc[mi][ni][2]), "+f"(acc[mi][ni][3])
                        : "r"(af[mi][0]), "r"(af[mi][1]), "r"(af[mi][2]), "r"(af[mi][3]),
                          "r"(bfr[ni][0]), "r"(bfr[ni][1]));
        }
    }

    if (MODE == 0) {
#pragma unroll
        for (int mi = 0; mi < MF; mi++) {
            int row = bm0 + wm + mi * 16 + (lane >> 2);
#pragma unroll
            for (int h = 0; h < 2; h++) {
                int rr = row + h * 8;
                float rs = 0.f;
#pragma unroll
                for (int ni = 0; ni < NF; ni++) {
                    int col = bn0 + wn + ni * 8 + (lane & 3) * 2;
                    float b0v = __ldg(&bias[col]), b1v = __ldg(&bias[col + 1]);
                    __nv_bfloat162 p = __floats2bfloat162_rn(acc[mi][ni][2 * h] + b0v,
                                                             acc[mi][ni][2 * h + 1] + b1v);
                    *(__nv_bfloat162*)(osel + (size_t)rr * ldo + col) = p;
                    float x = __bfloat162float(p.x), y = __bfloat162float(p.y);
                    rs += x * x + y * y;
                }
                if (isq) {
                    rs += __shfl_xor_sync(~0u, rs, 1);
                    rs += __shfl_xor_sync(~0u, rs, 2);
                    if ((lane & 3) == 0) atomicAdd(&qnorm[rr], rs);
                }
            }
        }
    } else {  // MODE 2
#pragma unroll
        for (int mi = 0; mi < MF; mi++) {
            int row = bm0 + wm + mi * 16 + (lane >> 2);
#pragma unroll
            for (int h = 0; h < 2; h++) {
                int rr = row + 8 * h;
                float qn = __ldg(&qnorm[rr]);
#pragma unroll
                for (int ni = 0; ni < NF; ni++)
#pragma unroll
                    for (int j = 0; j < 2; j++) {
                        int c = wn + ni * 8 + (lane & 3) * 2 + j;
                        float d2 = qn + __ldg(&pnorm[c]) - 2.f * acc[mi][ni][2 * h + j];
                        outf[(size_t)rr * NCLS + c] = -sqrtf(fmaxf(d2, 1e-12f));
                    }
            }
        }
    }
}

// ---------------- host orchestration ----------------
extern "C" void kernel_launch(void* const* d_in, const int* in_sizes, int n_in,
                              void* d_out, int out_size) {
    (void)in_sizes; (void)n_in; (void)out_size;
    const float* support = (const float*)d_in[0];
    const float* query = (const float*)d_in[1];
    const int* slab = (const int*)d_in[2];
    const float* W = (const float*)d_in[3];
    const float* bias = (const float*)d_in[4];
    float* out = (float*)d_out;

    __nv_bfloat16 *Wt, *qx, *sx, *qemb, *semb, *pb;
    float *qnorm, *ssum, *scount, *qsum, *qcount, *pnorm;
    cudaGetSymbolAddress((void**)&Wt, g_Wt);
    cudaGetSymbolAddress((void**)&qx, g_qx);
    cudaGetSymbolAddress((void**)&sx, g_sx);
    cudaGetSymbolAddress((void**)&qemb, g_qemb);
    cudaGetSymbolAddress((void**)&semb, g_semb);
    cudaGetSymbolAddress((void**)&qnorm, g_qnorm);
    cudaGetSymbolAddress((void**)&ssum, g_ssum);
    cudaGetSymbolAddress((void**)&scount, g_scount);
    cudaGetSymbolAddress((void**)&qsum, g_qsum);
    cudaGetSymbolAddress((void**)&qcount, g_qcount);
    cudaGetSymbolAddress((void**)&pb, g_pb);
    cudaGetSymbolAddress((void**)&pnorm, g_pnorm);

    const int SMEM_BIG = 3 * (128 + 256) * 128;   // 147456
    const int SMEM_SML = 3 * (128 + 64) * 128;    // 73728
    cudaFuncSetAttribute(k_gemm<128, 256, 2, 4, 0>, cudaFuncAttributeMaxDynamicSharedMemorySize, SMEM_BIG);
    cudaFuncSetAttribute(k_gemm<128, 64, 4, 2, 2>, cudaFuncAttributeMaxDynamicSharedMemorySize, SMEM_SML);
    cudaFuncSetAttribute(k_step, cudaFuncAttributeMaxDynamicSharedMemorySize, STP_SMEM);

    // launch order: 1=prep, 2=big GEMM, 3=supp_proto, 4=FIRST k_step (profiled)
    k_prep<<<QB_PREP + SB_PREP + TB_PREP, 256>>>(query, support, W, qx, sx, Wt, qnorm);

    k_gemm<128, 256, 2, 4, 0><<<dim3(DEMB / 256, QYB + NSUP / 128), 256, SMEM_BIG>>>(
        qx, Wt, DIN, bias, qemb, DEMB, nullptr, qnorm, nullptr, sx, semb, QYB);

    k_supp_proto<<<NCLS, 256>>>(semb, slab, ssum, scount, qsum, qcount, pb, pnorm);

    for (int s = 0; s < NSTEPS; s++) {
        k_step<<<dim3(1, NQRY / 256), 256, STP_SMEM>>>(qemb, pb, pnorm, qsum, qcount);
        k_proto<<<NCLS, 256>>>(ssum, scount, qsum, qcount, pb, pnorm);
    }

    // final logits
    k_gemm<128, 64, 4, 2, 2><<<dim3(1, NQRY / 128), 256, SMEM_SML>>>(
        qemb, pb, DEMB, nullptr, nullptr, 0, pnorm, qnorm, out, nullptr, nullptr, 1 << 20);
}

// round 13
// speedup vs baseline: 1.5890x; 1.1684x over previous
#include <cuda_runtime.h>
#include <cuda_bf16.h>
#include <stdint.h>

#define NSUP   1280
#define NQRY   65536
#define DIN    2048
#define DEMB   1024
#define NCLS   64
#define NSTEPS 5
#define QYB    (NQRY / 128)   // 512 query y-blocks

// ---------------- scratch (device globals; no allocation) ----------------
__device__ __align__(256) __nv_bfloat16 g_Wt[(size_t)DEMB * DIN];      // [DEMB][DIN]
__device__ __align__(256) __nv_bfloat16 g_qx[(size_t)NQRY * DIN];
__device__ __align__(256) __nv_bfloat16 g_sx[(size_t)NSUP * DIN];
__device__ __align__(256) __nv_bfloat16 g_qemb[(size_t)NQRY * DEMB];
__device__ __align__(256) __nv_bfloat16 g_semb[(size_t)NSUP * DEMB];
__device__ float g_qnorm[NQRY];
__device__ float g_ssum[NCLS * DEMB];
__device__ float g_scount[NCLS];
__device__ __align__(16) float g_qsum[NCLS * DEMB];
__device__ float g_qcount[NCLS];
__device__ __align__(256) __nv_bfloat16 g_pb[NCLS * DEMB];             // prototypes bf16
__device__ float g_pnorm[NCLS];

#define CP_ASYNC(dst, src) asm volatile("cp.async.cg.shared.global [%0], [%1], 16;\n" ::"r"(dst), "l"(src))
#define RED_V4(ptr, v) \
    asm volatile("red.global.add.v4.f32 [%0], {%1,%2,%3,%4};" \
                 ::"l"(ptr), "f"((v).x), "f"((v).y), "f"((v).z), "f"((v).w) : "memory")

// ---------------- fused prep: converts + W transpose + qnorm zero ----------------
#define QB_PREP (NQRY * DIN / 4 / 256)   // 131072
#define SB_PREP (NSUP * DIN / 4 / 256)   // 2560
#define TB_PREP (DIN / 32 * DEMB / 32)   // 2048

__global__ void __launch_bounds__(256) k_prep(
    const float* __restrict__ query, const float* __restrict__ support,
    const float* __restrict__ W, __nv_bfloat16* __restrict__ qx,
    __nv_bfloat16* __restrict__ sx, __nv_bfloat16* __restrict__ Wt,
    float* __restrict__ qnorm) {
    __shared__ float tile[32][33];
    int b = blockIdx.x;
    int tid = threadIdx.x;
    if (b < QB_PREP + SB_PREP) {
        const float* src = (b < QB_PREP) ? query : support;
        __nv_bfloat16* dst = (b < QB_PREP) ? qx : sx;
        int i = (b < QB_PREP ? b : b - QB_PREP) * 256 + tid;
        float4 v = ((const float4*)src)[i];
        ((__nv_bfloat162*)dst)[2 * i + 0] = __floats2bfloat162_rn(v.x, v.y);
        ((__nv_bfloat162*)dst)[2 * i + 1] = __floats2bfloat162_rn(v.z, v.w);
    } else {
        int tb = b - QB_PREP - SB_PREP;          // 0..2047
        int n0 = (tb & 31) * 32;
        int k0 = (tb >> 5) * 32;
        int tx = tid & 31, ty = tid >> 5;        // 32 x 8
#pragma unroll
        for (int i = 0; i < 4; i++) {
            int k = k0 + ty + i * 8;
            tile[ty + i * 8][tx] = W[(size_t)k * DEMB + n0 + tx];
        }
        if (tid < 32) qnorm[tb * 32 + tid] = 0.f;
        __syncthreads();
#pragma unroll
        for (int i = 0; i < 4; i++) {
            int n = n0 + ty + i * 8;
            Wt[(size_t)n * DIN + k0 + tx] = __float2bfloat16(tile[tx][ty + i * 8]);
        }
    }
}

// ---------------- fused support stats + initial prototypes ----------------
__global__ void __launch_bounds__(256) k_supp_proto(
    const __nv_bfloat16* __restrict__ semb, const int* __restrict__ lab,
    float* __restrict__ ssum, float* __restrict__ scount,
    float* __restrict__ qsum, float* __restrict__ qcount,
    __nv_bfloat16* __restrict__ pb, float* __restrict__ pnorm) {
    int c = blockIdx.x;
    int tid = threadIdx.x;
    __shared__ short labs[NSUP];
    for (int i = tid; i < NSUP; i += 256) labs[i] = (short)__ldg(&lab[i]);
    __syncthreads();
    float a0 = 0.f, a1 = 0.f, a2 = 0.f, a3 = 0.f;
    int cnt = 0;
    for (int r = 0; r < NSUP; r++) {
        if (labs[r] == c) {
            cnt++;
            const __nv_bfloat16* row = semb + (size_t)r * DEMB + tid * 4;
            __nv_bfloat162 v0 = *(const __nv_bfloat162*)(row);
            __nv_bfloat162 v1 = *(const __nv_bfloat162*)(row + 2);
            float2 f0 = __bfloat1622float2(v0), f1 = __bfloat1622float2(v1);
            a0 += f0.x; a1 += f0.y; a2 += f1.x; a3 += f1.y;
        }
    }
    float inv = 1.f / fmaxf((float)cnt, 1.f);
    int j = c * DEMB + tid * 4;
    ssum[j] = a0; ssum[j + 1] = a1; ssum[j + 2] = a2; ssum[j + 3] = a3;
    qsum[j] = 0.f; qsum[j + 1] = 0.f; qsum[j + 2] = 0.f; qsum[j + 3] = 0.f;
    __nv_bfloat16 p0 = __float2bfloat16(a0 * inv), p1 = __float2bfloat16(a1 * inv);
    __nv_bfloat16 p2 = __float2bfloat16(a2 * inv), p3 = __float2bfloat16(a3 * inv);
    pb[j] = p0; pb[j + 1] = p1; pb[j + 2] = p2; pb[j + 3] = p3;
    float f0 = __bfloat162float(p0), f1 = __bfloat162float(p1);
    float f2 = __bfloat162float(p2), f3 = __bfloat162float(p3);
    float s = f0 * f0 + f1 * f1 + f2 * f2 + f3 * f3;
    __shared__ float red[8];
#pragma unroll
    for (int o2 = 16; o2; o2 >>= 1) s += __shfl_xor_sync(~0u, s, o2);
    if ((tid & 31) == 0) red[tid >> 5] = s;
    __syncthreads();
    if (tid < 8) {
        s = red[tid];
#pragma unroll
        for (int o2 = 4; o2; o2 >>= 1) s += __shfl_xor_sync(0xff, s, o2);
        if (tid == 0) {
            pnorm[c] = s;
            scount[c] = (float)cnt;
            qcount[c] = 0.f;
        }
    }
}

// prototypes from (ssum + qsum) / counts; ALSO zeroes qsum/qcount for the next pass.
__global__ void k_proto(const float* __restrict__ ssum, const float* __restrict__ scount,
                        float* __restrict__ qsum, float* __restrict__ qcount,
                        __nv_bfloat16* __restrict__ pb, float* __restrict__ pnorm) {
    int c = blockIdx.x;
    float cnt = scount[c] + qcount[c];
    float inv = 1.f / fmaxf(cnt, 1.f);
    float s = 0.f;
    for (int j = threadIdx.x; j < DEMB; j += blockDim.x) {
        float p = (ssum[c * DEMB + j] + qsum[c * DEMB + j]) * inv;
        qsum[c * DEMB + j] = 0.f;
        __nv_bfloat16 pv = __float2bfloat16(p);
        pb[c * DEMB + j] = pv;
        float pf = __bfloat162float(pv);
        s += pf * pf;
    }
    if (threadIdx.x == 0) qcount[c] = 0.f;
    __shared__ float red[8];
#pragma unroll
    for (int o2 = 16; o2; o2 >>= 1) s += __shfl_xor_sync(~0u, s, o2);
    if ((threadIdx.x & 31) == 0) red[threadIdx.x >> 5] = s;
    __syncthreads();
    if (threadIdx.x < 8) {
        s = red[threadIdx.x];
#pragma unroll
        for (int o2 = 4; o2; o2 >>= 1) s += __shfl_xor_sync(0xff, s, o2);
        if (threadIdx.x == 0) pnorm[c] = s;
    }
}

// ================= fused transductive step =================
// R8 structure; CHANGES: 4 smem stages (depth-3 cp.async pipeline) and
// double-buffered register staging in phase B (MLP up, same accumulation order).
#define STP_STAGE ((256 + 64) * 128)   // 40960 B per stage (A 32KB + B 8KB)
#define STP_SMEM  (4 * STP_STAGE)      // 163840 B (>= bins 131072)

__global__ void __launch_bounds__(256, 1) k_step(
    const __nv_bfloat16* __restrict__ qemb, const __nv_bfloat16* __restrict__ pb,
    const float* __restrict__ pnorm, float* __restrict__ qsum, float* __restrict__ qcount) {
    extern __shared__ char smem_raw[];
    uint32_t sbase = (uint32_t)__cvta_generic_to_shared(smem_raw);
    __shared__ short labels_s[256];
    __shared__ int hist[NCLS];

    const int tid = threadIdx.x;
    const int warp = tid >> 5, lane = tid & 31;
    const int wm = warp * 32;                 // WM=32, WN=64 (all classes)
    const int bm0 = blockIdx.y * 256;
    const __nv_bfloat16* A = qemb + (size_t)bm0 * DEMB;

    if (tid < NCLS) hist[tid] = 0;

    float acc[2][8][4];
#pragma unroll
    for (int i = 0; i < 2; i++)
#pragma unroll
        for (int j = 0; j < 8; j++)
#pragma unroll
            for (int q = 0; q < 4; q++) acc[i][j][q] = 0.f;

    const int KT = DEMB >> 6;  // 16

    auto load = [&](int kt) {
        uint32_t sA = sbase + (kt & 3) * STP_STAGE;
        uint32_t sB = sA + 256u * 128u;
        const __nv_bfloat16* Ap = A + (size_t)kt * 64;
        const __nv_bfloat16* Bp = pb + (size_t)kt * 64;
#pragma unroll
        for (int i = 0; i < 8; i++) {
            int idx = tid + i * 256;
            int r = idx >> 3, c = idx & 7;
            CP_ASYNC(sA + (uint32_t)(r * 128 + ((c ^ (r & 7)) * 16)), Ap + (size_t)r * DEMB + c * 8);
        }
#pragma unroll
        for (int i = 0; i < 2; i++) {
            int idx = tid + i * 256;
            int r = idx >> 3, c = idx & 7;
            CP_ASYNC(sB + (uint32_t)(r * 128 + ((c ^ (r & 7)) * 16)), Bp + (size_t)r * DEMB + c * 8);
        }
        asm volatile("cp.async.commit_group;\n");
    };

    // depth-3 pipeline over 4 stages
    load(0);
    load(1);
    load(2);
    for (int kt = 0; kt < KT; kt++) {
        if (kt < KT - 2)
            asm volatile("cp.async.wait_group 2;\n" ::: "memory");
        else if (kt < KT - 1)
            asm volatile("cp.async.wait_group 1;\n" ::: "memory");
        else
            asm volatile("cp.async.wait_group 0;\n" ::: "memory");
        __syncthreads();
        if (kt + 3 < KT) load(kt + 3);  // writes stage (kt-1)&3: drained by sync above
        uint32_t aBase = sbase + (kt & 3) * STP_STAGE;
        uint32_t bBase = aBase + 256u * 128u;
#pragma unroll
        for (int ks = 0; ks < 4; ks++) {
            uint32_t af[2][4];
#pragma unroll
            for (int mi = 0; mi < 2; mi++) {
                int row = wm + mi * 16 + (lane & 15);
                int ch = (ks * 2 + (lane >> 4)) ^ (row & 7);
                uint32_t adr = aBase + (uint32_t)(row * 128 + ch * 16);
                asm volatile("ldmatrix.sync.aligned.m8n8.x4.shared.b16 {%0,%1,%2,%3},[%4];"
                             : "=r"(af[mi][0]), "=r"(af[mi][1]), "=r"(af[mi][2]), "=r"(af[mi][3])
                             : "r"(adr));
            }
            uint32_t bfr[8][2];
#pragma unroll
            for (int ni2 = 0; ni2 < 4; ni2++) {
                int nrow = ni2 * 16 + (lane & 7) + ((lane >> 4) << 3);
                int ch = (ks * 2 + ((lane >> 3) & 1)) ^ (nrow & 7);
                uint32_t bd = bBase + (uint32_t)(nrow * 128 + ch * 16);
                uint32_t r0, r1, r2, r3;
                asm volatile("ldmatrix.sync.aligned.m8n8.x4.shared.b16 {%0,%1,%2,%3},[%4];"
                             : "=r"(r0), "=r"(r1), "=r"(r2), "=r"(r3)
                             : "r"(bd));
                bfr[2 * ni2][0] = r0; bfr[2 * ni2][1] = r1;
                bfr[2 * ni2 + 1][0] = r2; bfr[2 * ni2 + 1][1] = r3;
            }
#pragma unroll
            for (int mi = 0; mi < 2; mi++)
#pragma unroll
                for (int ni = 0; ni < 8; ni++)
                    asm volatile(
                        "mma.sync.aligned.m16n8k16.row.col.f32.bf16.bf16.f32 "
                        "{%0,%1,%2,%3},{%4,%5,%6,%7},{%8,%9},{%0,%1,%2,%3};"
                        : "+f"(acc[mi][ni][0]), "+f"(acc[mi][ni][1]),
                          "+f"(acc[mi][ni][2]), "+f"(acc[mi][ni][3])
                        : "r"(af[mi][0]), "r"(af[mi][1]), "r"(af[mi][2]), "r"(af[mi][3]),
                          "r"(bfr[ni][0]), "r"(bfr[ni][1]));
        }
    }

    // argmin over 64 classes (margin = pnorm - 2*dot), tie -> lowest index
    {
        float bv[2][2];
        int bc[2][2];
#pragma unroll
        for (int mi = 0; mi < 2; mi++)
#pragma unroll
            for (int h = 0; h < 2; h++) { bv[mi][h] = 1e30f; bc[mi][h] = 0; }
#pragma unroll
        for (int ni = 0; ni < 8; ni++)
#pragma unroll
            for (int j = 0; j < 2; j++) {
                int c = ni * 8 + (lane & 3) * 2 + j;
                float pn = __ldg(&pnorm[c]);
#pragma unroll
                for (int mi = 0; mi < 2; mi++)
#pragma unroll
                    for (int h = 0; h < 2; h++) {
                        float m = pn - 2.f * acc[mi][ni][2 * h + j];
                        if (m < bv[mi][h]) { bv[mi][h] = m; bc[mi][h] = c; }
                    }
            }
#pragma unroll
        for (int off = 1; off <= 2; off <<= 1)
#pragma unroll
            for (int mi = 0; mi < 2; mi++)
#pragma unroll
                for (int h = 0; h < 2; h++) {
                    float ov = __shfl_xor_sync(~0u, bv[mi][h], off);
                    int oc = __shfl_xor_sync(~0u, bc[mi][h], off);
                    if (ov < bv[mi][h] || (ov == bv[mi][h] && oc < bc[mi][h])) {
                        bv[mi][h] = ov; bc[mi][h] = oc;
                    }
                }
        if ((lane & 3) == 0) {
#pragma unroll
            for (int mi = 0; mi < 2; mi++)
#pragma unroll
                for (int h = 0; h < 2; h++) {
                    int row = wm + mi * 16 + (lane >> 2) + 8 * h;
                    labels_s[row] = (short)bc[mi][h];
                    atomicAdd(&hist[bc[mi][h]], 1);
                }
        }
    }
    __syncthreads();
    if (tid < NCLS) atomicAdd(&qcount[tid], (float)hist[tid]);

    // ---- Phase B: per-class accumulate of own 256 rows ----
    // bins[rg][cls][cp]: 4 row-groups x 64 classes x 64 float2 = 128KB
    float2* bins = (float2*)smem_raw;
    float4* bins4 = (float4*)smem_raw;   // [rg][cls][32 float4]
    const int rg = tid >> 6;        // 0..3 (rows rg*64 .. rg*64+63)
    const int cp = tid & 63;        // bf162 column within 64-pair chunk
    const __nv_bfloat162* q2 = (const __nv_bfloat162*)(qemb) + (size_t)bm0 * 512;
    for (int i = tid; i < 4 * NCLS * 64; i += 256) {
        bins[i].x = 0.f; bins[i].y = 0.f;
    }
    __syncthreads();
#pragma unroll 1
    for (int chunk = 0; chunk < 8; chunk++) {
        float2* mybins = bins + rg * NCLS * 64 + cp;
        float2 bufA[4], bufB[4];
        short lA[4], lB[4];
        auto loadgrp = [&](float2* buf, short* ls, int g) {
#pragma unroll
            for (int j = 0; j < 4; j++) {
                int row = rg * 64 + g * 4 + j;
                ls[j] = labels_s[row];
                buf[j] = __bfloat1622float2(q2[(size_t)row * 512 + chunk * 64 + cp]);
            }
        };
        auto accum = [&](float2* buf, short* ls) {
#pragma unroll
            for (int j = 0; j < 4; j++) {
                float2* b = mybins + ls[j] * 64;
                b->x += buf[j].x;
                b->y += buf[j].y;
            }
        };
        loadgrp(bufA, lA, 0);
#pragma unroll
        for (int g = 0; g < 16; g += 2) {
            if (g + 1 < 16) loadgrp(bufB, lB, g + 1);
            accum(bufA, lA);
            if (g + 2 < 16) loadgrp(bufA, lA, g + 2);
            if (g + 1 < 16) accum(bufB, lB);
        }
        __syncthreads();
        const float4 z4 = make_float4(0.f, 0.f, 0.f, 0.f);
        for (int i = tid; i < NCLS * 32; i += 256) {
            int cls = i >> 5, c4 = i & 31;
            float4 s0 = bins4[(0 * NCLS + cls) * 32 + c4];
            float4 s1 = bins4[(1 * NCLS + cls) * 32 + c4];
            float4 s2 = bins4[(2 * NCLS + cls) * 32 + c4];
            float4 s3 = bins4[(3 * NCLS + cls) * 32 + c4];
            bins4[(0 * NCLS + cls) * 32 + c4] = z4;
            bins4[(1 * NCLS + cls) * 32 + c4] = z4;
            bins4[(2 * NCLS + cls) * 32 + c4] = z4;
            bins4[(3 * NCLS + cls) * 32 + c4] = z4;
            float4 v;
            v.x = s0.x + s1.x + s2.x + s3.x;
            v.y = s0.y + s1.y + s2.y + s3.y;
            v.z = s0.z + s1.z + s2.z + s3.z;
            v.w = s0.w + s1.w + s2.w + s3.w;
            RED_V4(&qsum[cls * DEMB + chunk * 128 + c4 * 4], v);
        }
        __syncthreads();
    }
}

// ---------------- bf16 HMMA GEMM (embedding + logits) ----------------
template <int BM, int BN, int WMT, int WNT, int MODE>
__global__ void __launch_bounds__(WMT* WNT * 32, 1) k_gemm(
    const __nv_bfloat16* __restrict__ A, const __nv_bfloat16* __restrict__ B, int K,
    const float* __restrict__ bias, __nv_bfloat16* __restrict__ outb, int ldo,
    const float* __restrict__ pnorm, float* __restrict__ qnorm, float* __restrict__ outf,
    const __nv_bfloat16* __restrict__ A2, __nv_bfloat16* __restrict__ outb2, int nqy) {
    constexpr int NT = WMT * WNT * 32;
    constexpr int WM = BM / WMT, WN = BN / WNT;
    constexpr int MF = WM / 16, NF = WN / 8;
    constexpr int AIT = BM * 8 / NT;
    constexpr int BIT = BN * 8 / NT;
    constexpr uint32_t STAGE = (BM + BN) * 128;

    extern __shared__ char smem_raw[];
    uint32_t sbase = (uint32_t)__cvta_generic_to_shared(smem_raw);

    const int tid = threadIdx.x;
    const int warp = tid >> 5, lane = tid & 31;
    const int wm = (warp / WNT) * WM, wn = (warp % WNT) * WN;
    const int bn0 = blockIdx.x * BN;

    bool isq = true;
    int ybase = blockIdx.y;
    const __nv_bfloat16* Asel = A;
    __nv_bfloat16* osel = outb;
    if (MODE == 0 && (int)blockIdx.y >= nqy) {
        isq = false;
        ybase = blockIdx.y - nqy;
        Asel = A2;
        osel = outb2;
    }
    const int bm0 = ybase * BM;

    const __nv_bfloat16* Ab = Asel + (size_t)bm0 * K;
    const __nv_bfloat16* Bb = B + (size_t)bn0 * K;

    float acc[MF][NF][4];
#pragma unroll
    for (int i = 0; i < MF; i++)
#pragma unroll
        for (int j = 0; j < NF; j++)
#pragma unroll
            for (int q = 0; q < 4; q++) acc[i][j][q] = 0.f;

    const int KT = K >> 6;

    auto load = [&](int kt) {
        uint32_t sA = sbase + (kt % 3) * STAGE;
        uint32_t sB = sA + (uint32_t)BM * 128u;
        const __nv_bfloat16* Ap = Ab + (size_t)kt * 64;
        const __nv_bfloat16* Bp = Bb + (size_t)kt * 64;
#pragma unroll
        for (int i = 0; i < AIT; i++) {
            int idx = tid + i * NT;
            int r = idx >> 3, c = idx & 7;
            CP_ASYNC(sA + (uint32_t)(r * 128 + ((c ^ (r & 7)) * 16)), Ap + (size_t)r * K + c * 8);
        }
#pragma unroll
        for (int i = 0; i < BIT; i++) {
            int idx = tid + i * NT;
            int r = idx >> 3, c = idx & 7;
            CP_ASYNC(sB + (uint32_t)(r * 128 + ((c ^ (r & 7)) * 16)), Bp + (size_t)r * K + c * 8);
        }
        asm volatile("cp.async.commit_group;\n");
    };

    load(0);
    load(1);
    for (int kt = 0; kt < KT; kt++) {
        if (kt < KT - 1)
            asm volatile("cp.async.wait_group 1;\n" ::: "memory");
        else
            asm volatile("cp.async.wait_group 0;\n" ::: "memory");
        __syncthreads();
        if (kt + 2 < KT) load(kt + 2);
        uint32_t aBase = sbase + (kt % 3) * STAGE;
        uint32_t bBase = aBase + (uint32_t)BM * 128u;
#pragma unroll
        for (int ks = 0; ks < 4; ks++) {
            uint32_t af[MF][4];
#pragma unroll
            for (int mi = 0; mi < MF; mi++) {
                int row = wm + mi * 16 + (lane & 15);
                int ch = (ks * 2 + (lane >> 4)) ^ (row & 7);
                uint32_t adr = aBase + (uint32_t)(row * 128 + ch * 16);
                asm volatile("ldmatrix.sync.aligned.m8n8.x4.shared.b16 {%0,%1,%2,%3},[%4];"
                             : "=r"(af[mi][0]), "=r"(af[mi][1]), "=r"(af[mi][2]), "=r"(af[mi][3])
                             : "r"(adr));
            }
            uint32_t bfr[NF][2];
#pragma unroll
            for (int ni2 = 0; ni2 < NF / 2; ni2++) {
                int nrow = wn + ni2 * 16 + (lane & 7) + ((lane >> 4) << 3);
                int ch = (ks * 2 + ((lane >> 3) & 1)) ^ (nrow & 7);
                uint32_t bd = bBase + (uint32_t)(nrow * 128 + ch * 16);
                uint32_t r0, r1, r2, r3;
                asm volatile("ldmatrix.sync.aligned.m8n8.x4.shared.b16 {%0,%1,%2,%3},[%4];"
                             : "=r"(r0), "=r"(r1), "=r"(r2), "=r"(r3)
                             : "r"(bd));
                bfr[2 * ni2][0] = r0; bfr[2 * ni2][1] = r1;
                bfr[2 * ni2 + 1][0] = r2; bfr[2 * ni2 + 1][1] = r3;
            }
#pragma unroll
            for (int mi = 0; mi < MF; mi++)
#pragma unroll
                for (int ni = 0; ni < NF; ni++)
                    asm volatile(
                        "mma.sync.aligned.m16n8k16.row.col.f32.bf16.bf16.f32 "
                        "{%0,%1,%2,%3},{%4,%5,%6,%7},{%8,%9},{%0,%1,%2,%3};"
                        : "+f"(acc[mi][ni][0]), "+f"(acc[mi][ni][1]),
                          "+f"(acc[mi][ni][2]), "+f"(acc[mi][ni][3])
                        : "r"(af[mi][0]), "r"(af[mi][1]), "r"(af[mi][2]), "r"(af[mi][3]),
                          "r"(bfr[ni][0]), "r"(bfr[ni][1]));
        }
    }

    if (MODE == 0) {
#pragma unroll
        for (int mi = 0; mi < MF; mi++) {
            int row = bm0 + wm + mi * 16 + (lane >> 2);
#pragma unroll
            for (int h = 0; h < 2; h++) {
                int rr = row + h * 8;
                float rs = 0.f;
#pragma unroll
                for (int ni = 0; ni < NF; ni++) {
                    int col = bn0 + wn + ni * 8 + (lane & 3) * 2;
                    float b0v = __ldg(&bias[col]), b1v = __ldg(&bias[col + 1]);
                    __nv_bfloat162 p = __floats2bfloat162_rn(acc[mi][ni][2 * h] + b0v,
                                                             acc[mi][ni][2 * h + 1] + b1v);
                    *(__nv_bfloat162*)(osel + (size_t)rr * ldo + col) = p;
                    float x = __bfloat162float(p.x), y = __bfloat162float(p.y);
                    rs += x * x + y * y;
                }
                if (isq) {
                    rs += __shfl_xor_sync(~0u, rs, 1);
                    rs += __shfl_xor_sync(~0u, rs, 2);
                    if ((lane & 3) == 0) atomicAdd(&qnorm[rr], rs);
                }
            }
        }
    } else {  // MODE 2
#pragma unroll
        for (int mi = 0; mi < MF; mi++) {
            int row = bm0 + wm + mi * 16 + (lane >> 2);
#pragma unroll
            for (int h = 0; h < 2; h++) {
                int rr = row + 8 * h;
                float qn = __ldg(&qnorm[rr]);
#pragma unroll
                for (int ni = 0; ni < NF; ni++)
#pragma unroll
                    for (int j = 0; j < 2; j++) {
                        int c = wn + ni * 8 + (lane & 3) * 2 + j;
                        float d2 = qn + __ldg(&pnorm[c]) - 2.f * acc[mi][ni][2 * h + j];
                        outf[(size_t)rr * NCLS + c] = -sqrtf(fmaxf(d2, 1e-12f));
                    }
            }
        }
    }
}

// ---------------- host orchestration ----------------
extern "C" void kernel_launch(void* const* d_in, const int* in_sizes, int n_in,
                              void* d_out, int out_size) {
    (void)in_sizes; (void)n_in; (void)out_size;
    const float* support = (const float*)d_in[0];
    const float* query = (const float*)d_in[1];
    const int* slab = (const int*)d_in[2];
    const float* W = (const float*)d_in[3];
    const float* bias = (const float*)d_in[4];
    float* out = (float*)d_out;

    __nv_bfloat16 *Wt, *qx, *sx, *qemb, *semb, *pb;
    float *qnorm, *ssum, *scount, *qsum, *qcount, *pnorm;
    cudaGetSymbolAddress((void**)&Wt, g_Wt);
    cudaGetSymbolAddress((void**)&qx, g_qx);
    cudaGetSymbolAddress((void**)&sx, g_sx);
    cudaGetSymbolAddress((void**)&qemb, g_qemb);
    cudaGetSymbolAddress((void**)&semb, g_semb);
    cudaGetSymbolAddress((void**)&qnorm, g_qnorm);
    cudaGetSymbolAddress((void**)&ssum, g_ssum);
    cudaGetSymbolAddress((void**)&scount, g_scount);
    cudaGetSymbolAddress((void**)&qsum, g_qsum);
    cudaGetSymbolAddress((void**)&qcount, g_qcount);
    cudaGetSymbolAddress((void**)&pb, g_pb);
    cudaGetSymbolAddress((void**)&pnorm, g_pnorm);

    const int SMEM_BIG = 3 * (128 + 256) * 128;   // 147456
    const int SMEM_SML = 3 * (128 + 64) * 128;    // 73728
    cudaFuncSetAttribute(k_gemm<128, 256, 2, 4, 0>, cudaFuncAttributeMaxDynamicSharedMemorySize, SMEM_BIG);
    cudaFuncSetAttribute(k_gemm<128, 64, 4, 2, 2>, cudaFuncAttributeMaxDynamicSharedMemorySize, SMEM_SML);
    cudaFuncSetAttribute(k_step, cudaFuncAttributeMaxDynamicSharedMemorySize, STP_SMEM);

    // launch order: 1=prep, 2=big GEMM, 3=supp_proto, 4=FIRST k_step (profiled)
    k_prep<<<QB_PREP + SB_PREP + TB_PREP, 256>>>(query, support, W, qx, sx, Wt, qnorm);

    k_gemm<128, 256, 2, 4, 0><<<dim3(DEMB / 256, QYB + NSUP / 128), 256, SMEM_BIG>>>(
        qx, Wt, DIN, bias, qemb, DEMB, nullptr, qnorm, nullptr, sx, semb, QYB);

    k_supp_proto<<<NCLS, 256>>>(semb, slab, ssum, scount, qsum, qcount, pb, pnorm);

    for (int s = 0; s < NSTEPS; s++) {
        k_step<<<dim3(1, NQRY / 256), 256, STP_SMEM>>>(qemb, pb, pnorm, qsum, qcount);
        k_proto<<<NCLS, 256>>>(ssum, scount, qsum, qcount, pb, pnorm);
    }

    // final logits
    k_gemm<128, 64, 4, 2, 2><<<dim3(1, NQRY / 128), 256, SMEM_SML>>>(
        qemb, pb, DEMB, nullptr, nullptr, 0, pnorm, qnorm, out, nullptr, nullptr, 1 << 20);
}